// round 6
// baseline (speedup 1.0000x reference)
#include <cuda_runtime.h>
#include <cstdint>

#define BB   4
#define N1   16384
#define N2   4096
#define CC   128
#define CIN  384
#define CH   256
#define TN   64
#define KC   32
#define SXS  72          // sX / sY row stride in floats: 72 % 32 == 8 -> conflict-free frag loads
#define SWS  264         // sW row stride in floats: 264 % 32 == 8
#define SEG  8
#define SEGN (N2 / SEG)  // 512

#define SX_FLOATS   (CIN * SXS)          // 27648
#define SW_FLOATS   (KC * SWS)           // 8448  (one buffer)
#define NBUF        3
#define NCHUNK      20                   // 12 for GEMM1 + 8 for GEMM2
#define SMEM_MLP_BYTES ((SX_FLOATS + NBUF * SW_FLOATS + TN) * 4)  // 212224

// ------------------- scratch (device globals; no allocation) -------------------
__device__ float4 g_xyz2n[BB * N2];          // packed xyz2 + |x|^2
__device__ float4 g_w4[BB * N1];             // normalized 3-NN weights
__device__ int4   g_i4[BB * N1];             // 3-NN indices
__device__ float4 g_pd[BB * SEG * N1];       // per-segment partial top-3 scores
__device__ int4   g_pi[BB * SEG * N1];       // per-segment partial top-3 indices
__device__ float  g_p2t[BB * N2 * CC];       // points2 transposed (B, N2, C)
__device__ float  g_W0t[CIN * CH];           // folded W0, transposed (k, oc), tf32-rounded
__device__ float  g_W1t[CH * CH];            // folded W1, transposed (k, oc), tf32-rounded
__device__ float  g_b0f[CH];
__device__ float  g_b1f[CH];

// ------------------- helpers -------------------
__device__ __forceinline__ float cvt_tf32(float x) {
    unsigned u;
    asm("cvt.rna.tf32.f32 %0, %1;" : "=r"(u) : "f"(x));
    return __uint_as_float(u);
}

__device__ __forceinline__ void mma8(float* d, const unsigned* a, const unsigned* b) {
    asm("mma.sync.aligned.m16n8k8.row.col.f32.tf32.tf32.f32 "
        "{%0,%1,%2,%3}, {%4,%5,%6,%7}, {%8,%9}, {%0,%1,%2,%3};\n"
        : "+f"(d[0]), "+f"(d[1]), "+f"(d[2]), "+f"(d[3])
        : "r"(a[0]), "r"(a[1]), "r"(a[2]), "r"(a[3]), "r"(b[0]), "r"(b[1]));
}

__device__ __forceinline__ void cp16(float* s, const float* g) {
    unsigned sa = (unsigned)__cvta_generic_to_shared(s);
    asm volatile("cp.async.cg.shared.global [%0], [%1], 16;\n" :: "r"(sa), "l"(g));
}
#define CP_COMMIT() asm volatile("cp.async.commit_group;\n")
#define CP_WAIT1()  asm volatile("cp.async.wait_group 1;\n")
#define CP_WAIT0()  asm volatile("cp.async.wait_group 0;\n")

// ------------------- K1: fold BN into weights (tf32-rounded), transpose -------------------
__global__ void fold_kernel(const float* __restrict__ w0, const float* __restrict__ b0,
                            const float* __restrict__ g0, const float* __restrict__ be0,
                            const float* __restrict__ m0, const float* __restrict__ v0,
                            const float* __restrict__ w1, const float* __restrict__ b1,
                            const float* __restrict__ g1, const float* __restrict__ be1,
                            const float* __restrict__ m1, const float* __restrict__ v1) {
    int t = blockIdx.x * blockDim.x + threadIdx.x;
    if (t < CH * CIN) {
        int o = t / CIN, c = t % CIN;
        float s = g0[o] * rsqrtf(v0[o] + 1e-5f);
        g_W0t[c * CH + o] = cvt_tf32(w0[t] * s);
    }
    if (t < CH * CH) {
        int o = t / CH, c = t % CH;
        float s = g1[o] * rsqrtf(v1[o] + 1e-5f);
        g_W1t[c * CH + o] = cvt_tf32(w1[t] * s);
    }
    if (t < CH) {
        float s0 = g0[t] * rsqrtf(v0[t] + 1e-5f);
        g_b0f[t] = (b0[t] - m0[t]) * s0 + be0[t];
        float s1 = g1[t] * rsqrtf(v1[t] + 1e-5f);
        g_b1f[t] = (b1[t] - m1[t]) * s1 + be1[t];
    }
}

// ------------------- K2: pack xyz2 with norms -------------------
__global__ void pack_kernel(const float* __restrict__ xyz2) {
    int t = blockIdx.x * blockDim.x + threadIdx.x;
    if (t < BB * N2) {
        float x = xyz2[3 * t], y = xyz2[3 * t + 1], z = xyz2[3 * t + 2];
        g_xyz2n[t] = make_float4(x, y, z, x * x + y * y + z * z);
    }
}

// ------------------- K3: transpose points2 (B,C,N2) -> (B,N2,C) -------------------
__global__ void transpose_kernel(const float* __restrict__ p2) {
    __shared__ float tile[32][33];
    int b = blockIdx.z;
    int nb = blockIdx.x * 32, cb = blockIdx.y * 32;
    int tx = threadIdx.x, ty = threadIdx.y;  // (32, 8)
    #pragma unroll
    for (int i = 0; i < 32; i += 8)
        tile[ty + i][tx] = p2[((size_t)b * CC + cb + ty + i) * N2 + nb + tx];
    __syncthreads();
    #pragma unroll
    for (int i = 0; i < 32; i += 8)
        g_p2t[((size_t)b * N2 + nb + ty + i) * CC + cb + tx] = tile[tx][ty + i];
}

// ------------------- top-3 insertion -------------------
__device__ __forceinline__ void ins3(float s, int j,
                                     float& a0, float& a1, float& a2,
                                     int& i0, int& i1, int& i2) {
    if (s < a2) {
        if (s < a1) {
            a2 = a1; i2 = i1;
            if (s < a0) { a1 = a0; i1 = i0; a0 = s; i0 = j; }
            else        { a1 = s;  i1 = j; }
        } else { a2 = s; i2 = j; }
    }
}

// ------------------- K4a: segmented 3-NN partials -------------------
__global__ void __launch_bounds__(256) knn_part(const float* __restrict__ xyz1) {
    __shared__ float4 sP[SEGN];     // 8 KB
    int b = blockIdx.z, seg = blockIdx.y;
    int t = threadIdx.x;
    for (int i = t; i < SEGN; i += 256) sP[i] = g_xyz2n[b * N2 + seg * SEGN + i];
    __syncthreads();

    int q0 = blockIdx.x * 512 + t;
    int q1 = q0 + 256;
    const float* p0 = xyz1 + ((size_t)b * N1 + q0) * 3;
    const float* p1 = xyz1 + ((size_t)b * N1 + q1) * 3;
    float ax0 = -2.f * p0[0], ay0 = -2.f * p0[1], az0 = -2.f * p0[2];
    float ax1 = -2.f * p1[0], ay1 = -2.f * p1[1], az1 = -2.f * p1[2];

    float A0 = 3.0e38f, A1 = 3.0e38f, A2 = 3.0e38f;
    float B0 = 3.0e38f, B1 = 3.0e38f, B2 = 3.0e38f;
    int   I0 = 0, I1 = 0, I2 = 0, J0 = 0, J1 = 0, J2 = 0;

    #pragma unroll 8
    for (int j = 0; j < SEGN; j++) {
        float4 p = sP[j];
        float s0 = fmaf(ax0, p.x, fmaf(ay0, p.y, fmaf(az0, p.z, p.w)));
        ins3(s0, j, A0, A1, A2, I0, I1, I2);
        float s1 = fmaf(ax1, p.x, fmaf(ay1, p.y, fmaf(az1, p.z, p.w)));
        ins3(s1, j, B0, B1, B2, J0, J1, J2);
    }

    int base = seg * SEGN;
    size_t o0 = (size_t)(b * SEG + seg) * N1 + q0;
    size_t o1 = (size_t)(b * SEG + seg) * N1 + q1;
    g_pd[o0] = make_float4(A0, A1, A2, 0.f);
    g_pi[o0] = make_int4(base + I0, base + I1, base + I2, 0);
    g_pd[o1] = make_float4(B0, B1, B2, 0.f);
    g_pi[o1] = make_int4(base + J0, base + J1, base + J2, 0);
}

// ------------------- K4b: merge partials, compute interp weights -------------------
__global__ void knn_merge(const float* __restrict__ xyz1) {
    int t = blockIdx.x * blockDim.x + threadIdx.x;   // 0 .. BB*N1
    if (t >= BB * N1) return;
    int b = t / N1, q = t % N1;

    float A0 = 3.0e38f, A1 = 3.0e38f, A2 = 3.0e38f;
    int   I0 = 0, I1 = 0, I2 = 0;
    #pragma unroll
    for (int s = 0; s < SEG; s++) {
        size_t o = (size_t)(b * SEG + s) * N1 + q;
        float4 d = g_pd[o];
        int4   i = g_pi[o];
        ins3(d.x, i.x, A0, A1, A2, I0, I1, I2);
        ins3(d.y, i.y, A0, A1, A2, I0, I1, I2);
        ins3(d.z, i.z, A0, A1, A2, I0, I1, I2);
    }
    float x = xyz1[3 * t], y = xyz1[3 * t + 1], z = xyz1[3 * t + 2];
    float nq = x * x + y * y + z * z;
    float w0 = 1.f / (nq + A0), w1 = 1.f / (nq + A1), w2 = 1.f / (nq + A2);
    float inv = 1.f / (w0 + w1 + w2);
    g_w4[t] = make_float4(w0 * inv, w1 * inv, w2 * inv, 0.f);
    g_i4[t] = make_int4(I0, I1, I2, 0);
}

// ------------------- MLP building blocks -------------------
__device__ __forceinline__ void issue_w(int cc, int tid, float* sW) {
    const float* src = (cc < 12) ? (g_W0t + (size_t)cc * 32 * CH)
                                 : (g_W1t + (size_t)(cc - 12) * 32 * CH);
    float* dst = sW + (cc % NBUF) * SW_FLOATS;
    #pragma unroll
    for (int i = 0; i < 8; i++) {
        int f4 = tid + i * 256;          // 2048 float4 per chunk
        int kk = f4 >> 6, oc4 = f4 & 63;
        cp16(dst + kk * SWS + oc4 * 4, src + kk * CH + oc4 * 4);
    }
    CP_COMMIT();
}

__device__ __forceinline__ void gemm_chunk(const float* sWb, const float* sB,
                                           int warp, int lane, float acc[2][8][4]) {
    int grp = lane >> 2, tig = lane & 3, Rw = warp * 32;
    #pragma unroll
    for (int ks = 0; ks < 4; ks++) {
        int k8 = ks * 8;
        unsigned a[2][4], bf[8][2];
        const float* w0r = sWb + (k8 + tig) * SWS;
        const float* w4r = sWb + (k8 + tig + 4) * SWS;
        #pragma unroll
        for (int m = 0; m < 2; m++) {
            int rb = Rw + m * 16 + grp;
            a[m][0] = __float_as_uint(w0r[rb]);
            a[m][1] = __float_as_uint(w0r[rb + 8]);
            a[m][2] = __float_as_uint(w4r[rb]);
            a[m][3] = __float_as_uint(w4r[rb + 8]);
        }
        const float* x0r = sB + (k8 + tig) * SXS;
        const float* x4r = sB + (k8 + tig + 4) * SXS;
        #pragma unroll
        for (int j = 0; j < 8; j++) {
            int cb = j * 8 + grp;
            bf[j][0] = __float_as_uint(x0r[cb]);
            bf[j][1] = __float_as_uint(x4r[cb]);
        }
        #pragma unroll
        for (int m = 0; m < 2; m++)
            #pragma unroll
            for (int j = 0; j < 8; j++)
                mma8(acc[m][j], a[m], bf[j]);
    }
}

// ------------------- K5: fused concat + 2x (GEMM + BN + ReLU) + channel max -------------------
__global__ void __launch_bounds__(256, 1)
mlp_kernel(const float* __restrict__ points1, const float* __restrict__ pb1,
           float* __restrict__ out) {
    extern __shared__ float sm[];
    float* sX   = sm;                                   // [384][SXS]; reused as sY
    float* sW   = sm + SX_FLOATS;                       // 3 x [KC][SWS]
    int*   sOutI = (int*)(sm + SX_FLOATS + NBUF * SW_FLOATS);  // [TN]

    int b  = blockIdx.y;
    int n0 = blockIdx.x * TN;
    int tid = threadIdx.x;
    int warp = tid >> 5, lane = tid & 31;
    int grp = lane >> 2, tig = lane & 3;
    int Rw = warp * 32;

    // prefetch first two W chunks while building X
    issue_w(0, tid, sW);
    issue_w(1, tid, sW);

    // ---- Phase A: build X tile (384 x 64) in smem ----
    for (int idx = tid; idx < CC * TN; idx += 256) {
        int c = idx >> 6, n = idx & 63;
        sX[c * SXS + n]         = cvt_tf32(points1[((size_t)b * CC + c) * N1 + n0 + n]);
        sX[(c + 256) * SXS + n] = cvt_tf32(pb1[((size_t)b * CC + c) * N1 + n0 + n]);
    }
    // fused section rows 128..255 (each warp handles 8 queries; coalesced row gathers)
    for (int qq = 0; qq < 8; qq++) {
        int q = warp * 8 + qq;
        int n = n0 + q;
        float4 wv = g_w4[b * N1 + n];
        int4   iv = g_i4[b * N1 + n];
        const float* r0 = &g_p2t[((size_t)b * N2 + iv.x) * CC];
        const float* r1 = &g_p2t[((size_t)b * N2 + iv.y) * CC];
        const float* r2 = &g_p2t[((size_t)b * N2 + iv.z) * CC];
        #pragma unroll
        for (int i = 0; i < 4; i++) {
            int c = lane + 32 * i;
            float v = wv.x * r0[c] + wv.y * r1[c] + wv.z * r2[c];
            sX[(128 + c) * SXS + q] = cvt_tf32(v);
        }
    }

    // ---- GEMM1: y0(256x64) = W0'(256x384) * X, pipelined over 12 chunks ----
    float acc[2][8][4];
    #pragma unroll
    for (int m = 0; m < 2; m++)
        #pragma unroll
        for (int j = 0; j < 8; j++)
            #pragma unroll
            for (int e = 0; e < 4; e++) acc[m][j][e] = 0.f;

    for (int cc = 0; cc < 12; cc++) {
        CP_WAIT1();
        __syncthreads();     // chunk cc visible to all; also covers Phase A at cc=0
        gemm_chunk(sW + (cc % NBUF) * SW_FLOATS, sX + cc * 32 * SXS, warp, lane, acc);
        issue_w(cc + 2, tid, sW);   // into buf[(cc+2)%3]: safe, all passed this iter's bar
    }

    // ---- epilogue 1: bias + ReLU -> sY (rows 0..255 of sX region) ----
    // No pre-bar needed: last chunk's compute reads only rows 352..383; sY is rows 0..255.
    {
        float bz[4];
        #pragma unroll
        for (int i = 0; i < 4; i++) bz[i] = g_b0f[Rw + grp + 8 * i];
        float* sY = sm;
        #pragma unroll
        for (int m = 0; m < 2; m++)
            #pragma unroll
            for (int j = 0; j < 8; j++) {
                int r0 = Rw + 16 * m + grp;
                int col = 8 * j + 2 * tig;
                sY[r0 * SXS + col]           = cvt_tf32(fmaxf(acc[m][j][0] + bz[2 * m], 0.f));
                sY[r0 * SXS + col + 1]       = cvt_tf32(fmaxf(acc[m][j][1] + bz[2 * m], 0.f));
                sY[(r0 + 8) * SXS + col]     = cvt_tf32(fmaxf(acc[m][j][2] + bz[2 * m + 1], 0.f));
                sY[(r0 + 8) * SXS + col + 1] = cvt_tf32(fmaxf(acc[m][j][3] + bz[2 * m + 1], 0.f));
            }
    }

    // ---- GEMM2: y1(256x64) = W1'(256x256) * y0, pipelined over 8 chunks ----
    float ac2[2][8][4];
    #pragma unroll
    for (int m = 0; m < 2; m++)
        #pragma unroll
        for (int j = 0; j < 8; j++)
            #pragma unroll
            for (int e = 0; e < 4; e++) ac2[m][j][e] = 0.f;

    for (int cc = 12; cc < NCHUNK; cc++) {
        if (cc < NCHUNK - 1) { CP_WAIT1(); } else { CP_WAIT0(); }
        __syncthreads();     // chunk cc + epilogue-1 sY visible to all
        gemm_chunk(sW + (cc % NBUF) * SW_FLOATS, sm + (cc - 12) * 32 * SXS, warp, lane, ac2);
        if (cc + 2 < NCHUNK) issue_w(cc + 2, tid, sW);
    }

    // ---- epilogue 2: bias + ReLU + max over 256 channels ----
    float bz1[4];
    #pragma unroll
    for (int i = 0; i < 4; i++) bz1[i] = g_b1f[Rw + grp + 8 * i];

    if (tid < TN) sOutI[tid] = 0;   // ReLU output >= 0 -> int 0 is valid identity
    __syncthreads();

    #pragma unroll
    for (int j = 0; j < 8; j++) {
        #pragma unroll
        for (int e = 0; e < 2; e++) {
            int col = 8 * j + 2 * tig + e;
            float v =    fmaxf(ac2[0][j][e]     + bz1[0], 0.f);
            v = fmaxf(v, fmaxf(ac2[0][j][e + 2] + bz1[1], 0.f));
            v = fmaxf(v, fmaxf(ac2[1][j][e]     + bz1[2], 0.f));
            v = fmaxf(v, fmaxf(ac2[1][j][e + 2] + bz1[3], 0.f));
            v = fmaxf(v, __shfl_xor_sync(0xffffffffu, v, 4));
            v = fmaxf(v, __shfl_xor_sync(0xffffffffu, v, 8));
            v = fmaxf(v, __shfl_xor_sync(0xffffffffu, v, 16));
            if (grp == 0) atomicMax(&sOutI[col], __float_as_int(v));
        }
    }
    __syncthreads();
    if (tid < TN) out[(size_t)b * N1 + n0 + tid] = __int_as_float(sOutI[tid]);
}

// ------------------- launch -------------------
extern "C" void kernel_launch(void* const* d_in, const int* in_sizes, int n_in,
                              void* d_out, int out_size) {
    const float* xyz1    = (const float*)d_in[0];
    const float* xyz2    = (const float*)d_in[1];
    const float* points2 = (const float*)d_in[2];
    const float* points1 = (const float*)d_in[3];
    const float* pb1     = (const float*)d_in[4];
    const float* w0  = (const float*)d_in[5];
    const float* b0  = (const float*)d_in[6];
    const float* g0  = (const float*)d_in[7];
    const float* be0 = (const float*)d_in[8];
    const float* m0  = (const float*)d_in[9];
    const float* v0  = (const float*)d_in[10];
    const float* w1  = (const float*)d_in[11];
    const float* b1  = (const float*)d_in[12];
    const float* g1  = (const float*)d_in[13];
    const float* be1 = (const float*)d_in[14];
    const float* m1  = (const float*)d_in[15];
    const float* v1  = (const float*)d_in[16];
    float* out = (float*)d_out;

    cudaFuncSetAttribute(mlp_kernel, cudaFuncAttributeMaxDynamicSharedMemorySize,
                         SMEM_MLP_BYTES);

    fold_kernel<<<(CH * CIN + 255) / 256, 256>>>(w0, b0, g0, be0, m0, v0,
                                                 w1, b1, g1, be1, m1, v1);
    pack_kernel<<<(BB * N2 + 255) / 256, 256>>>(xyz2);
    transpose_kernel<<<dim3(N2 / 32, CC / 32, BB), dim3(32, 8)>>>(points2);
    knn_part<<<dim3(N1 / 512, SEG, BB), 256>>>(xyz1);
    knn_merge<<<(BB * N1 + 255) / 256, 256>>>(xyz1);
    mlp_kernel<<<dim3(N1 / TN, BB), 256, SMEM_MLP_BYTES>>>(points1, pb1, out);
}

// round 7
// speedup vs baseline: 1.1870x; 1.1870x over previous
#include <cuda_runtime.h>
#include <cstdint>
#include <climits>

#define BB   4
#define N1   16384
#define N2   4096
#define CC   128
#define CIN  384
#define CH   256
#define TN   64
#define KC   32
#define SXS  72
#define SWS  264
#define SEG  4
#define SEGN (N2 / SEG)          // 1024 candidates, 256 quads per segment
#define QMASK 0xFFFFFF00u

#define SX_FLOATS   (CIN * SXS)
#define SW_FLOATS   (KC * SWS)
#define NBUF        3
#define NCHUNK      20
#define SMEM_MLP_BYTES ((SX_FLOATS + NBUF * SW_FLOATS + TN) * 4)  // 212224

// ------------------- scratch -------------------
__device__ float4 g_xyz2n[BB * N2];
__device__ uint4  g_pk[BB * SEG * N1];       // per-segment top-3 quad keys
__device__ float4 g_w4[BB * N1];
__device__ int4   g_i4[BB * N1];
__device__ float  g_p2t[BB * N2 * CC];
__device__ float  g_W0t[CIN * CH];
__device__ float  g_W1t[CH * CH];
__device__ float  g_b0f[CH];
__device__ float  g_b1f[CH];

// ------------------- helpers -------------------
__device__ __forceinline__ float cvt_tf32(float x) {
    unsigned u;
    asm("cvt.rna.tf32.f32 %0, %1;" : "=r"(u) : "f"(x));
    return __uint_as_float(u);
}

__device__ __forceinline__ void mma8(float* d, const unsigned* a, const unsigned* b) {
    asm("mma.sync.aligned.m16n8k8.row.col.f32.tf32.tf32.f32 "
        "{%0,%1,%2,%3}, {%4,%5,%6,%7}, {%8,%9}, {%0,%1,%2,%3};\n"
        : "+f"(d[0]), "+f"(d[1]), "+f"(d[2]), "+f"(d[3])
        : "r"(a[0]), "r"(a[1]), "r"(a[2]), "r"(a[3]), "r"(b[0]), "r"(b[1]));
}

__device__ __forceinline__ void cp16(float* s, const float* g) {
    unsigned sa = (unsigned)__cvta_generic_to_shared(s);
    asm volatile("cp.async.cg.shared.global [%0], [%1], 16;\n" :: "r"(sa), "l"(g));
}
#define CP_COMMIT() asm volatile("cp.async.commit_group;\n")
#define CP_WAIT1()  asm volatile("cp.async.wait_group 1;\n")
#define CP_WAIT0()  asm volatile("cp.async.wait_group 0;\n")

// sorted-3 insert over signed-int keys; keeps K0<=K1<=K2 (5 min/max ops)
__device__ __forceinline__ void kins3(int k, int& K0, int& K1, int& K2) {
    int t0 = min(K0, k), u0 = max(K0, k);
    int t1 = min(K1, u0), u1 = max(K1, u0);
    K2 = min(K2, u1); K0 = t0; K1 = t1;
}

// float top-3 insertion with index
__device__ __forceinline__ void ins3(float s, int j,
                                     float& a0, float& a1, float& a2,
                                     int& i0, int& i1, int& i2) {
    if (s < a2) {
        if (s < a1) {
            a2 = a1; i2 = i1;
            if (s < a0) { a1 = a0; i1 = i0; a0 = s; i0 = j; }
            else        { a1 = s;  i1 = j; }
        } else { a2 = s; i2 = j; }
    }
}

// ------------------- K1: fold BN into weights -------------------
__global__ void fold_kernel(const float* __restrict__ w0, const float* __restrict__ b0,
                            const float* __restrict__ g0, const float* __restrict__ be0,
                            const float* __restrict__ m0, const float* __restrict__ v0,
                            const float* __restrict__ w1, const float* __restrict__ b1,
                            const float* __restrict__ g1, const float* __restrict__ be1,
                            const float* __restrict__ m1, const float* __restrict__ v1) {
    int t = blockIdx.x * blockDim.x + threadIdx.x;
    if (t < CH * CIN) {
        int o = t / CIN, c = t % CIN;
        float s = g0[o] * rsqrtf(v0[o] + 1e-5f);
        g_W0t[c * CH + o] = cvt_tf32(w0[t] * s);
    }
    if (t < CH * CH) {
        int o = t / CH, c = t % CH;
        float s = g1[o] * rsqrtf(v1[o] + 1e-5f);
        g_W1t[c * CH + o] = cvt_tf32(w1[t] * s);
    }
    if (t < CH) {
        float s0 = g0[t] * rsqrtf(v0[t] + 1e-5f);
        g_b0f[t] = (b0[t] - m0[t]) * s0 + be0[t];
        float s1 = g1[t] * rsqrtf(v1[t] + 1e-5f);
        g_b1f[t] = (b1[t] - m1[t]) * s1 + be1[t];
    }
}

// ------------------- K2: pack xyz2 with norms -------------------
__global__ void pack_kernel(const float* __restrict__ xyz2) {
    int t = blockIdx.x * blockDim.x + threadIdx.x;
    if (t < BB * N2) {
        float x = xyz2[3 * t], y = xyz2[3 * t + 1], z = xyz2[3 * t + 2];
        g_xyz2n[t] = make_float4(x, y, z, x * x + y * y + z * z);
    }
}

// ------------------- K3: transpose points2 -------------------
__global__ void transpose_kernel(const float* __restrict__ p2) {
    __shared__ float tile[32][33];
    int b = blockIdx.z;
    int nb = blockIdx.x * 32, cb = blockIdx.y * 32;
    int tx = threadIdx.x, ty = threadIdx.y;
    #pragma unroll
    for (int i = 0; i < 32; i += 8)
        tile[ty + i][tx] = p2[((size_t)b * CC + cb + ty + i) * N2 + nb + tx];
    __syncthreads();
    #pragma unroll
    for (int i = 0; i < 32; i += 8)
        g_p2t[((size_t)b * N2 + nb + ty + i) * CC + cb + tx] = tile[tx][ty + i];
}

// ------------------- K4a: quad-min 3-NN scan -------------------
__global__ void __launch_bounds__(256) knn_part(const float* __restrict__ xyz1) {
    __shared__ float4 sP[SEGN];      // 16 KB
    int b = blockIdx.z, seg = blockIdx.y;
    int t = threadIdx.x;
    for (int i = t; i < SEGN; i += 256) sP[i] = g_xyz2n[b * N2 + seg * SEGN + i];
    __syncthreads();

    int q0 = blockIdx.x * 512 + t, q1 = q0 + 256;
    const float* p0 = xyz1 + ((size_t)b * N1 + q0) * 3;
    const float* p1 = xyz1 + ((size_t)b * N1 + q1) * 3;
    float x0 = p0[0], y0 = p0[1], z0 = p0[2];
    float x1 = p1[0], y1 = p1[1], z1 = p1[2];
    float ax0 = -2.f * x0, ay0 = -2.f * y0, az0 = -2.f * z0;
    float ax1 = -2.f * x1, ay1 = -2.f * y1, az1 = -2.f * z1;
    float nq0 = x0 * x0 + y0 * y0 + z0 * z0;
    float nq1 = x1 * x1 + y1 * y1 + z1 * z1;

    int A0 = INT_MAX, A1 = INT_MAX, A2 = INT_MAX;
    int B0 = INT_MAX, B1 = INT_MAX, B2 = INT_MAX;

    #pragma unroll 4
    for (int qd = 0; qd < SEGN / 4; qd++) {
        float4 pa = sP[4 * qd], pb = sP[4 * qd + 1];
        float4 pc = sP[4 * qd + 2], pe = sP[4 * qd + 3];
        // query 0
        float sa = fmaf(ax0, pa.x, fmaf(ay0, pa.y, fmaf(az0, pa.z, pa.w)));
        float sb = fmaf(ax0, pb.x, fmaf(ay0, pb.y, fmaf(az0, pb.z, pb.w)));
        float sc = fmaf(ax0, pc.x, fmaf(ay0, pc.y, fmaf(az0, pc.z, pc.w)));
        float se = fmaf(ax0, pe.x, fmaf(ay0, pe.y, fmaf(az0, pe.z, pe.w)));
        float m0 = fmaxf(fminf(fminf(sa, sb), fminf(sc, se)) + nq0, 0.f);
        kins3((int)((__float_as_uint(m0) & QMASK) | (unsigned)qd), A0, A1, A2);
        // query 1
        float ta = fmaf(ax1, pa.x, fmaf(ay1, pa.y, fmaf(az1, pa.z, pa.w)));
        float tb = fmaf(ax1, pb.x, fmaf(ay1, pb.y, fmaf(az1, pb.z, pb.w)));
        float tc = fmaf(ax1, pc.x, fmaf(ay1, pc.y, fmaf(az1, pc.z, pc.w)));
        float te = fmaf(ax1, pe.x, fmaf(ay1, pe.y, fmaf(az1, pe.z, pe.w)));
        float m1 = fmaxf(fminf(fminf(ta, tb), fminf(tc, te)) + nq1, 0.f);
        kins3((int)((__float_as_uint(m1) & QMASK) | (unsigned)qd), B0, B1, B2);
    }

    size_t o0 = (size_t)(b * SEG + seg) * N1 + q0;
    size_t o1 = (size_t)(b * SEG + seg) * N1 + q1;
    g_pk[o0] = make_uint4((unsigned)A0, (unsigned)A1, (unsigned)A2, 0u);
    g_pk[o1] = make_uint4((unsigned)B0, (unsigned)B1, (unsigned)B2, 0u);
}

// ------------------- K4b: pick top-3 quads globally, exact rescan of 12 -------------------
__global__ void knn_merge(const float* __restrict__ xyz1) {
    int t = blockIdx.x * blockDim.x + threadIdx.x;
    if (t >= BB * N1) return;
    int b = t / N1, q = t % N1;

    float D0 = 3.0e38f, D1 = 3.0e38f, D2 = 3.0e38f;
    int   G0 = 0, G1 = 0, G2 = 0;
    #pragma unroll
    for (int s = 0; s < SEG; s++) {
        uint4 k = g_pk[(size_t)(b * SEG + s) * N1 + q];
        unsigned kk[3] = {k.x, k.y, k.z};
        #pragma unroll
        for (int i = 0; i < 3; i++) {
            int gid = s * (SEGN / 4) + (int)(kk[i] & 255u);
            float d = __uint_as_float(kk[i] & QMASK);
            ins3(d, gid, D0, D1, D2, G0, G1, G2);
        }
    }

    float x = xyz1[3 * t], y = xyz1[3 * t + 1], z = xyz1[3 * t + 2];
    float nq = x * x + y * y + z * z;

    float A0 = 3.0e38f, A1 = 3.0e38f, A2 = 3.0e38f;
    int   I0 = 0, I1 = 0, I2 = 0;
    int gs[3] = {G0, G1, G2};
    #pragma unroll
    for (int i = 0; i < 3; i++) {
        int base = gs[i] * 4;
        #pragma unroll
        for (int c = 0; c < 4; c++) {
            float4 p = g_xyz2n[b * N2 + base + c];
            float d = nq + p.w - 2.f * (x * p.x + y * p.y + z * p.z);
            ins3(d, base + c, A0, A1, A2, I0, I1, I2);
        }
    }

    float w0 = 1.f / A0, w1 = 1.f / A1, w2 = 1.f / A2;
    float inv = 1.f / (w0 + w1 + w2);
    g_w4[t] = make_float4(w0 * inv, w1 * inv, w2 * inv, 0.f);
    g_i4[t] = make_int4(I0, I1, I2, 0);
}

// ------------------- MLP building blocks -------------------
__device__ __forceinline__ void issue_w(int cc, int tid, float* sW) {
    const float* src = (cc < 12) ? (g_W0t + (size_t)cc * 32 * CH)
                                 : (g_W1t + (size_t)(cc - 12) * 32 * CH);
    float* dst = sW + (cc % NBUF) * SW_FLOATS;
    #pragma unroll
    for (int i = 0; i < 8; i++) {
        int f4 = tid + i * 256;
        int kk = f4 >> 6, oc4 = f4 & 63;
        cp16(dst + kk * SWS + oc4 * 4, src + kk * CH + oc4 * 4);
    }
    CP_COMMIT();
}

__device__ __forceinline__ void gemm_chunk(const float* sWb, const float* sB,
                                           int warp, int lane, float acc[2][8][4]) {
    int grp = lane >> 2, tig = lane & 3, Rw = warp * 32;
    #pragma unroll
    for (int ks = 0; ks < 4; ks++) {
        int k8 = ks * 8;
        unsigned a[2][4], bf[8][2];
        const float* w0r = sWb + (k8 + tig) * SWS;
        const float* w4r = sWb + (k8 + tig + 4) * SWS;
        #pragma unroll
        for (int m = 0; m < 2; m++) {
            int rb = Rw + m * 16 + grp;
            a[m][0] = __float_as_uint(w0r[rb]);
            a[m][1] = __float_as_uint(w0r[rb + 8]);
            a[m][2] = __float_as_uint(w4r[rb]);
            a[m][3] = __float_as_uint(w4r[rb + 8]);
        }
        const float* x0r = sB + (k8 + tig) * SXS;
        const float* x4r = sB + (k8 + tig + 4) * SXS;
        #pragma unroll
        for (int j = 0; j < 8; j++) {
            int cb = j * 8 + grp;
            bf[j][0] = __float_as_uint(x0r[cb]);
            bf[j][1] = __float_as_uint(x4r[cb]);
        }
        #pragma unroll
        for (int m = 0; m < 2; m++)
            #pragma unroll
            for (int j = 0; j < 8; j++)
                mma8(acc[m][j], a[m], bf[j]);
    }
}

// ------------------- K5: fused MLP + channel max -------------------
__global__ void __launch_bounds__(256, 1)
mlp_kernel(const float* __restrict__ points1, const float* __restrict__ pb1,
           float* __restrict__ out) {
    extern __shared__ float sm[];
    float* sX   = sm;
    float* sW   = sm + SX_FLOATS;
    int*   sOutI = (int*)(sm + SX_FLOATS + NBUF * SW_FLOATS);

    int b  = blockIdx.y;
    int n0 = blockIdx.x * TN;
    int tid = threadIdx.x;
    int warp = tid >> 5, lane = tid & 31;
    int grp = lane >> 2, tig = lane & 3;
    int Rw = warp * 32;

    issue_w(0, tid, sW);
    issue_w(1, tid, sW);

    for (int idx = tid; idx < CC * TN; idx += 256) {
        int c = idx >> 6, n = idx & 63;
        sX[c * SXS + n]         = cvt_tf32(points1[((size_t)b * CC + c) * N1 + n0 + n]);
        sX[(c + 256) * SXS + n] = cvt_tf32(pb1[((size_t)b * CC + c) * N1 + n0 + n]);
    }
    for (int qq = 0; qq < 8; qq++) {
        int q = warp * 8 + qq;
        int n = n0 + q;
        float4 wv = g_w4[b * N1 + n];
        int4   iv = g_i4[b * N1 + n];
        const float* r0 = &g_p2t[((size_t)b * N2 + iv.x) * CC];
        const float* r1 = &g_p2t[((size_t)b * N2 + iv.y) * CC];
        const float* r2 = &g_p2t[((size_t)b * N2 + iv.z) * CC];
        #pragma unroll
        for (int i = 0; i < 4; i++) {
            int c = lane + 32 * i;
            float v = wv.x * r0[c] + wv.y * r1[c] + wv.z * r2[c];
            sX[(128 + c) * SXS + q] = cvt_tf32(v);
        }
    }

    float acc[2][8][4];
    #pragma unroll
    for (int m = 0; m < 2; m++)
        #pragma unroll
        for (int j = 0; j < 8; j++)
            #pragma unroll
            for (int e = 0; e < 4; e++) acc[m][j][e] = 0.f;

    for (int cc = 0; cc < 12; cc++) {
        CP_WAIT1();
        __syncthreads();
        gemm_chunk(sW + (cc % NBUF) * SW_FLOATS, sX + cc * 32 * SXS, warp, lane, acc);
        issue_w(cc + 2, tid, sW);
    }

    {
        float bz[4];
        #pragma unroll
        for (int i = 0; i < 4; i++) bz[i] = g_b0f[Rw + grp + 8 * i];
        float* sY = sm;
        #pragma unroll
        for (int m = 0; m < 2; m++)
            #pragma unroll
            for (int j = 0; j < 8; j++) {
                int r0 = Rw + 16 * m + grp;
                int col = 8 * j + 2 * tig;
                sY[r0 * SXS + col]           = cvt_tf32(fmaxf(acc[m][j][0] + bz[2 * m], 0.f));
                sY[r0 * SXS + col + 1]       = cvt_tf32(fmaxf(acc[m][j][1] + bz[2 * m], 0.f));
                sY[(r0 + 8) * SXS + col]     = cvt_tf32(fmaxf(acc[m][j][2] + bz[2 * m + 1], 0.f));
                sY[(r0 + 8) * SXS + col + 1] = cvt_tf32(fmaxf(acc[m][j][3] + bz[2 * m + 1], 0.f));
            }
    }

    float ac2[2][8][4];
    #pragma unroll
    for (int m = 0; m < 2; m++)
        #pragma unroll
        for (int j = 0; j < 8; j++)
            #pragma unroll
            for (int e = 0; e < 4; e++) ac2[m][j][e] = 0.f;

    for (int cc = 12; cc < NCHUNK; cc++) {
        if (cc < NCHUNK - 1) { CP_WAIT1(); } else { CP_WAIT0(); }
        __syncthreads();
        gemm_chunk(sW + (cc % NBUF) * SW_FLOATS, sm + (cc - 12) * 32 * SXS, warp, lane, ac2);
        if (cc + 2 < NCHUNK) issue_w(cc + 2, tid, sW);
    }

    float bz1[4];
    #pragma unroll
    for (int i = 0; i < 4; i++) bz1[i] = g_b1f[Rw + grp + 8 * i];

    if (tid < TN) sOutI[tid] = 0;
    __syncthreads();

    #pragma unroll
    for (int j = 0; j < 8; j++) {
        #pragma unroll
        for (int e = 0; e < 2; e++) {
            int col = 8 * j + 2 * tig + e;
            float v =    fmaxf(ac2[0][j][e]     + bz1[0], 0.f);
            v = fmaxf(v, fmaxf(ac2[0][j][e + 2] + bz1[1], 0.f));
            v = fmaxf(v, fmaxf(ac2[1][j][e]     + bz1[2], 0.f));
            v = fmaxf(v, fmaxf(ac2[1][j][e + 2] + bz1[3], 0.f));
            v = fmaxf(v, __shfl_xor_sync(0xffffffffu, v, 4));
            v = fmaxf(v, __shfl_xor_sync(0xffffffffu, v, 8));
            v = fmaxf(v, __shfl_xor_sync(0xffffffffu, v, 16));
            if (grp == 0) atomicMax(&sOutI[col], __float_as_int(v));
        }
    }
    __syncthreads();
    if (tid < TN) out[(size_t)b * N1 + n0 + tid] = __int_as_float(sOutI[tid]);
}

// ------------------- launch -------------------
extern "C" void kernel_launch(void* const* d_in, const int* in_sizes, int n_in,
                              void* d_out, int out_size) {
    const float* xyz1    = (const float*)d_in[0];
    const float* xyz2    = (const float*)d_in[1];
    const float* points2 = (const float*)d_in[2];
    const float* points1 = (const float*)d_in[3];
    const float* pb1     = (const float*)d_in[4];
    const float* w0  = (const float*)d_in[5];
    const float* b0  = (const float*)d_in[6];
    const float* g0  = (const float*)d_in[7];
    const float* be0 = (const float*)d_in[8];
    const float* m0  = (const float*)d_in[9];
    const float* v0  = (const float*)d_in[10];
    const float* w1  = (const float*)d_in[11];
    const float* b1  = (const float*)d_in[12];
    const float* g1  = (const float*)d_in[13];
    const float* be1 = (const float*)d_in[14];
    const float* m1  = (const float*)d_in[15];
    const float* v1  = (const float*)d_in[16];
    float* out = (float*)d_out;

    cudaFuncSetAttribute(mlp_kernel, cudaFuncAttributeMaxDynamicSharedMemorySize,
                         SMEM_MLP_BYTES);

    fold_kernel<<<(CH * CIN + 255) / 256, 256>>>(w0, b0, g0, be0, m0, v0,
                                                 w1, b1, g1, be1, m1, v1);
    pack_kernel<<<(BB * N2 + 255) / 256, 256>>>(xyz2);
    transpose_kernel<<<dim3(N2 / 32, CC / 32, BB), dim3(32, 8)>>>(points2);
    knn_part<<<dim3(N1 / 512, SEG, BB), 256>>>(xyz1);
    knn_merge<<<(BB * N1 + 255) / 256, 256>>>(xyz1);
    mlp_kernel<<<dim3(N1 / TN, BB), 256, SMEM_MLP_BYTES>>>(points1, pb1, out);
}

// round 9
// speedup vs baseline: 1.2054x; 1.0155x over previous
#include <cuda_runtime.h>
#include <cstdint>
#include <climits>

#define BB   4
#define N1   16384
#define N2   4096
#define CC   128
#define CIN  384
#define CH   256
#define TN   64
#define SEG  8
#define SEGN (N2 / SEG)          // 512 candidates, 128 quads per segment
#define QMASK 0xFFFFFF80u

#define SXS  72                  // X/Y row stride (floats): 72 % 32 == 8 -> conflict-free B frags
#define WT   1152                // per-warp per-buffer W tile: 32 oc x 36 floats (stride 36)
#define SX_FLOATS (CIN * SXS)    // 27648
#define SW_TOT    (8 * 3 * WT)   // 27648
#define SMEM_MLP_BYTES ((SX_FLOATS + SW_TOT + 64) * 4)   // 221440

// ------------------- scratch -------------------
__device__ float4 g_xyz2n[BB * N2];
__device__ uint4  g_pk[BB * SEG * N1];       // per-segment top-3 quad keys
__device__ float4 g_w4[BB * N1];
__device__ int4   g_i4[BB * N1];
__device__ float  g_p2t[BB * N2 * CC];
__device__ float  g_W0a[CH * CIN];           // folded W0 (oc, k) row-major, tf32
__device__ float  g_W1a[CH * CH];            // folded W1 (oc, k) row-major, tf32
__device__ float  g_b0f[CH];
__device__ float  g_b1f[CH];

// ------------------- helpers -------------------
__device__ __forceinline__ float cvt_tf32(float x) {
    unsigned u;
    asm("cvt.rna.tf32.f32 %0, %1;" : "=r"(u) : "f"(x));
    return __uint_as_float(u);
}

__device__ __forceinline__ void mma8(float* d, const unsigned* a, const unsigned* b) {
    asm("mma.sync.aligned.m16n8k8.row.col.f32.tf32.tf32.f32 "
        "{%0,%1,%2,%3}, {%4,%5,%6,%7}, {%8,%9}, {%0,%1,%2,%3};\n"
        : "+f"(d[0]), "+f"(d[1]), "+f"(d[2]), "+f"(d[3])
        : "r"(a[0]), "r"(a[1]), "r"(a[2]), "r"(a[3]), "r"(b[0]), "r"(b[1]));
}

__device__ __forceinline__ void cp16(float* s, const float* g) {
    unsigned sa = (unsigned)__cvta_generic_to_shared(s);
    asm volatile("cp.async.cg.shared.global [%0], [%1], 16;\n" :: "r"(sa), "l"(g));
}
#define CP_COMMIT() asm volatile("cp.async.commit_group;\n")
#define CPW1() asm volatile("cp.async.wait_group 1;\n")
#define CPW0() asm volatile("cp.async.wait_group 0;\n")

// sorted-3 insert over signed-int keys (5 min/max)
__device__ __forceinline__ void kins3(int k, int& K0, int& K1, int& K2) {
    int t0 = min(K0, k), u0 = max(K0, k);
    int t1 = min(K1, u0), u1 = max(K1, u0);
    K2 = min(K2, u1); K0 = t0; K1 = t1;
}
__device__ __forceinline__ void ins3(float s, int j,
                                     float& a0, float& a1, float& a2,
                                     int& i0, int& i1, int& i2) {
    if (s < a2) {
        if (s < a1) {
            a2 = a1; i2 = i1;
            if (s < a0) { a1 = a0; i1 = i0; a0 = s; i0 = j; }
            else        { a1 = s;  i1 = j; }
        } else { a2 = s; i2 = j; }
    }
}

// ------------------- K1: fold BN into weights, (oc,k) row-major, tf32 -------------------
__global__ void fold_kernel(const float* __restrict__ w0, const float* __restrict__ b0,
                            const float* __restrict__ g0, const float* __restrict__ be0,
                            const float* __restrict__ m0, const float* __restrict__ v0,
                            const float* __restrict__ w1, const float* __restrict__ b1,
                            const float* __restrict__ g1, const float* __restrict__ be1,
                            const float* __restrict__ m1, const float* __restrict__ v1) {
    int t = blockIdx.x * blockDim.x + threadIdx.x;
    if (t < CH * CIN) {
        int o = t / CIN;
        float s = g0[o] * rsqrtf(v0[o] + 1e-5f);
        g_W0a[t] = cvt_tf32(w0[t] * s);
    }
    if (t < CH * CH) {
        int o = t / CH;
        float s = g1[o] * rsqrtf(v1[o] + 1e-5f);
        g_W1a[t] = cvt_tf32(w1[t] * s);
    }
    if (t < CH) {
        float s0 = g0[t] * rsqrtf(v0[t] + 1e-5f);
        g_b0f[t] = (b0[t] - m0[t]) * s0 + be0[t];
        float s1 = g1[t] * rsqrtf(v1[t] + 1e-5f);
        g_b1f[t] = (b1[t] - m1[t]) * s1 + be1[t];
    }
}

// ------------------- K2: pack xyz2 with norms -------------------
__global__ void pack_kernel(const float* __restrict__ xyz2) {
    int t = blockIdx.x * blockDim.x + threadIdx.x;
    if (t < BB * N2) {
        float x = xyz2[3 * t], y = xyz2[3 * t + 1], z = xyz2[3 * t + 2];
        g_xyz2n[t] = make_float4(x, y, z, x * x + y * y + z * z);
    }
}

// ------------------- K3: transpose points2 -------------------
__global__ void transpose_kernel(const float* __restrict__ p2) {
    __shared__ float tile[32][33];
    int b = blockIdx.z;
    int nb = blockIdx.x * 32, cb = blockIdx.y * 32;
    int tx = threadIdx.x, ty = threadIdx.y;
    #pragma unroll
    for (int i = 0; i < 32; i += 8)
        tile[ty + i][tx] = p2[((size_t)b * CC + cb + ty + i) * N2 + nb + tx];
    __syncthreads();
    #pragma unroll
    for (int i = 0; i < 32; i += 8)
        g_p2t[((size_t)b * N2 + nb + ty + i) * CC + cb + tx] = tile[tx][ty + i];
}

// ------------------- K4a: quad-min 3-NN scan (SEG=8) -------------------
__global__ void __launch_bounds__(256) knn_part(const float* __restrict__ xyz1) {
    __shared__ float4 sP[SEGN];      // 8 KB
    int b = blockIdx.z, seg = blockIdx.y;
    int t = threadIdx.x;
    for (int i = t; i < SEGN; i += 256) sP[i] = g_xyz2n[b * N2 + seg * SEGN + i];
    __syncthreads();

    int q0 = blockIdx.x * 512 + t, q1 = q0 + 256;
    const float* p0 = xyz1 + ((size_t)b * N1 + q0) * 3;
    const float* p1 = xyz1 + ((size_t)b * N1 + q1) * 3;
    float x0 = p0[0], y0 = p0[1], z0 = p0[2];
    float x1 = p1[0], y1 = p1[1], z1 = p1[2];
    float ax0 = -2.f * x0, ay0 = -2.f * y0, az0 = -2.f * z0;
    float ax1 = -2.f * x1, ay1 = -2.f * y1, az1 = -2.f * z1;
    float nq0 = x0 * x0 + y0 * y0 + z0 * z0;
    float nq1 = x1 * x1 + y1 * y1 + z1 * z1;

    int A0 = INT_MAX, A1 = INT_MAX, A2 = INT_MAX;
    int B0 = INT_MAX, B1 = INT_MAX, B2 = INT_MAX;

    #pragma unroll 4
    for (int qd = 0; qd < SEGN / 4; qd++) {
        float4 pa = sP[4 * qd], pb = sP[4 * qd + 1];
        float4 pc = sP[4 * qd + 2], pe = sP[4 * qd + 3];
        float sa = fmaf(ax0, pa.x, fmaf(ay0, pa.y, fmaf(az0, pa.z, pa.w)));
        float sb = fmaf(ax0, pb.x, fmaf(ay0, pb.y, fmaf(az0, pb.z, pb.w)));
        float sc = fmaf(ax0, pc.x, fmaf(ay0, pc.y, fmaf(az0, pc.z, pc.w)));
        float se = fmaf(ax0, pe.x, fmaf(ay0, pe.y, fmaf(az0, pe.z, pe.w)));
        float m0 = fmaxf(fminf(fminf(sa, sb), fminf(sc, se)) + nq0, 0.f);
        kins3((int)((__float_as_uint(m0) & QMASK) | (unsigned)qd), A0, A1, A2);
        float ta = fmaf(ax1, pa.x, fmaf(ay1, pa.y, fmaf(az1, pa.z, pa.w)));
        float tb = fmaf(ax1, pb.x, fmaf(ay1, pb.y, fmaf(az1, pb.z, pb.w)));
        float tc = fmaf(ax1, pc.x, fmaf(ay1, pc.y, fmaf(az1, pc.z, pc.w)));
        float te = fmaf(ax1, pe.x, fmaf(ay1, pe.y, fmaf(az1, pe.z, pe.w)));
        float m1 = fmaxf(fminf(fminf(ta, tb), fminf(tc, te)) + nq1, 0.f);
        kins3((int)((__float_as_uint(m1) & QMASK) | (unsigned)qd), B0, B1, B2);
    }

    size_t o0 = (size_t)(b * SEG + seg) * N1 + q0;
    size_t o1 = (size_t)(b * SEG + seg) * N1 + q1;
    g_pk[o0] = make_uint4((unsigned)A0, (unsigned)A1, (unsigned)A2, 0u);
    g_pk[o1] = make_uint4((unsigned)B0, (unsigned)B1, (unsigned)B2, 0u);
}

// ------------------- K4b: global top-3 quads + exact rescan -------------------
__global__ void knn_merge(const float* __restrict__ xyz1) {
    int t = blockIdx.x * blockDim.x + threadIdx.x;
    if (t >= BB * N1) return;
    int b = t / N1, q = t % N1;

    float D0 = 3.0e38f, D1 = 3.0e38f, D2 = 3.0e38f;
    int   G0 = 0, G1 = 0, G2 = 0;
    #pragma unroll
    for (int s = 0; s < SEG; s++) {
        uint4 k = g_pk[(size_t)(b * SEG + s) * N1 + q];
        unsigned kk[3] = {k.x, k.y, k.z};
        #pragma unroll
        for (int i = 0; i < 3; i++) {
            int gid = s * (SEGN / 4) + (int)(kk[i] & 127u);
            float d = __uint_as_float(kk[i] & QMASK);
            ins3(d, gid, D0, D1, D2, G0, G1, G2);
        }
    }

    float x = xyz1[3 * t], y = xyz1[3 * t + 1], z = xyz1[3 * t + 2];
    float nq = x * x + y * y + z * z;

    float A0 = 3.0e38f, A1 = 3.0e38f, A2 = 3.0e38f;
    int   I0 = 0, I1 = 0, I2 = 0;
    int gs[3] = {G0, G1, G2};
    #pragma unroll
    for (int i = 0; i < 3; i++) {
        int base = gs[i] * 4;
        #pragma unroll
        for (int c = 0; c < 4; c++) {
            float4 p = g_xyz2n[b * N2 + base + c];
            float d = nq + p.w - 2.f * (x * p.x + y * p.y + z * p.z);
            ins3(d, base + c, A0, A1, A2, I0, I1, I2);
        }
    }

    float w0 = 1.f / A0, w1 = 1.f / A1, w2 = 1.f / A2;
    float inv = 1.f / (w0 + w1 + w2);
    g_w4[t] = make_float4(w0 * inv, w1 * inv, w2 * inv, 0.f);
    g_i4[t] = make_int4(I0, I1, I2, 0);
}

// ------------------- MLP building blocks -------------------
// Per-warp W chunk stream: warp's own 32 oc rows x 32 k, dest tile [oc][k] stride 36.
__device__ __forceinline__ void issue_w(int c, int warp, int lane, float* sW) {
    const float* src; int Ksrc, kc;
    if (c < 12) { src = g_W0a; Ksrc = CIN; kc = c * 32; }
    else        { src = g_W1a; Ksrc = CH;  kc = (c - 12) * 32; }
    float* dst = sW + warp * (3 * WT) + (c % 3) * WT;
    int Rw = warp * 32;
    #pragma unroll
    for (int i = 0; i < 8; i++) {
        int idx = lane + 32 * i;            // 0..255 = 32 oc x 8 k-quads
        int ocl = idx >> 3, kq = idx & 7;
        cp16(dst + ocl * 36 + kq * 4, src + (size_t)(Rw + ocl) * Ksrc + kc + kq * 4);
    }
    CP_COMMIT();
}

// A frags from per-warp [oc][k] stride-36 tile ((oc*4+k) % 32 distinct -> conflict-free)
__device__ __forceinline__ void gemm_chunk(const float* wt, const float* sB,
                                           int lane, float acc[2][8][4]) {
    int grp = lane >> 2, tig = lane & 3;
    #pragma unroll
    for (int ks = 0; ks < 4; ks++) {
        int k8 = ks * 8;
        unsigned a[2][4], bf[8][2];
        #pragma unroll
        for (int m = 0; m < 2; m++) {
            const float* r0 = wt + (m * 16 + grp) * 36;
            const float* r8 = wt + (m * 16 + grp + 8) * 36;
            a[m][0] = __float_as_uint(r0[k8 + tig]);
            a[m][1] = __float_as_uint(r8[k8 + tig]);
            a[m][2] = __float_as_uint(r0[k8 + tig + 4]);
            a[m][3] = __float_as_uint(r8[k8 + tig + 4]);
        }
        const float* x0r = sB + (k8 + tig) * SXS;
        const float* x4r = sB + (k8 + tig + 4) * SXS;
        #pragma unroll
        for (int j = 0; j < 8; j++) {
            int cb = j * 8 + grp;
            bf[j][0] = __float_as_uint(x0r[cb]);
            bf[j][1] = __float_as_uint(x4r[cb]);
        }
        #pragma unroll
        for (int m = 0; m < 2; m++)
            #pragma unroll
            for (int j = 0; j < 8; j++)
                mma8(acc[m][j], a[m], bf[j]);
    }
}

// ------------------- K5: fused MLP + channel max (warp-private W pipeline) -------------------
__global__ void __launch_bounds__(256, 1)
mlp_kernel(const float* __restrict__ points1, const float* __restrict__ pb1,
           float* __restrict__ out) {
    extern __shared__ float sm[];
    float* sX   = sm;                         // [384][SXS]; rows 0..255 reused as Y
    float* sW   = sm + SX_FLOATS;             // 8 warps x 3 bufs x WT
    int*   sOutI = (int*)(sm + SX_FLOATS + SW_TOT);

    int b  = blockIdx.y;
    int n0 = blockIdx.x * TN;
    int tid = threadIdx.x;
    int warp = tid >> 5, lane = tid & 31;
    int grp = lane >> 2, tig = lane & 3;
    int Rw = warp * 32;

    // per-warp prefetch of first two W chunks
    issue_w(0, warp, lane, sW);
    issue_w(1, warp, lane, sW);

    // ---- Phase A: build X (384 x 64) ----
    for (int idx = tid; idx < CC * TN; idx += 256) {
        int c = idx >> 6, n = idx & 63;
        sX[c * SXS + n]         = cvt_tf32(points1[((size_t)b * CC + c) * N1 + n0 + n]);
        sX[(c + 256) * SXS + n] = cvt_tf32(pb1[((size_t)b * CC + c) * N1 + n0 + n]);
    }
    for (int qq = 0; qq < 8; qq++) {
        int q = warp * 8 + qq;
        int n = n0 + q;
        float4 wv = g_w4[b * N1 + n];
        int4   iv = g_i4[b * N1 + n];
        const float* r0 = &g_p2t[((size_t)b * N2 + iv.x) * CC];
        const float* r1 = &g_p2t[((size_t)b * N2 + iv.y) * CC];
        const float* r2 = &g_p2t[((size_t)b * N2 + iv.z) * CC];
        #pragma unroll
        for (int i = 0; i < 4; i++) {
            int c = lane + 32 * i;
            float v = wv.x * r0[c] + wv.y * r1[c] + wv.z * r2[c];
            sX[(128 + c) * SXS + q] = cvt_tf32(v);
        }
    }
    __syncthreads();

    // ---- GEMM1: barrier-free, per-warp W pipeline over 12 chunks ----
    float acc[2][8][4];
    #pragma unroll
    for (int m = 0; m < 2; m++)
        #pragma unroll
        for (int j = 0; j < 8; j++)
            #pragma unroll
            for (int e = 0; e < 4; e++) acc[m][j][e] = 0.f;

    for (int c = 0; c < 12; c++) {
        CPW1();
        gemm_chunk(sW + warp * (3 * WT) + (c % 3) * WT, sX + c * 32 * SXS, lane, acc);
        issue_w(c + 2, warp, lane, sW);
    }
    __syncthreads();   // all warps done reading X rows 0..255 before Y overwrites them

    // ---- epilogue 1: bias + ReLU -> Y (rows 0..255 of sX region, warp's own rows) ----
    {
        float bz[4];
        #pragma unroll
        for (int i = 0; i < 4; i++) bz[i] = g_b0f[Rw + grp + 8 * i];
        float* sY = sm;
        #pragma unroll
        for (int m = 0; m < 2; m++)
            #pragma unroll
            for (int j = 0; j < 8; j++) {
                int r0 = Rw + 16 * m + grp;
                int col = 8 * j + 2 * tig;
                sY[r0 * SXS + col]           = cvt_tf32(fmaxf(acc[m][j][0] + bz[2 * m], 0.f));
                sY[r0 * SXS + col + 1]       = cvt_tf32(fmaxf(acc[m][j][1] + bz[2 * m], 0.f));
                sY[(r0 + 8) * SXS + col]     = cvt_tf32(fmaxf(acc[m][j][2] + bz[2 * m + 1], 0.f));
                sY[(r0 + 8) * SXS + col + 1] = cvt_tf32(fmaxf(acc[m][j][3] + bz[2 * m + 1], 0.f));
            }
    }
    __syncthreads();   // Y visible to all before GEMM2 reads

    // ---- GEMM2: barrier-free, chunks 12..19 ----
    float ac2[2][8][4];
    #pragma unroll
    for (int m = 0; m < 2; m++)
        #pragma unroll
        for (int j = 0; j < 8; j++)
            #pragma unroll
            for (int e = 0; e < 4; e++) ac2[m][j][e] = 0.f;

    for (int c = 12; c < 20; c++) {
        if (c == 19) { CPW0(); } else { CPW1(); }
        gemm_chunk(sW + warp * (3 * WT) + (c % 3) * WT, sm + (c - 12) * 32 * SXS, lane, ac2);
        if (c + 2 < 20) issue_w(c + 2, warp, lane, sW);
    }

    // ---- epilogue 2: bias + ReLU + channel max ----
    float bz1[4];
    #pragma unroll
    for (int i = 0; i < 4; i++) bz1[i] = g_b1f[Rw + grp + 8 * i];

    if (tid < TN) sOutI[tid] = 0;   // ReLU output >= 0 -> int 0 valid identity
    __syncthreads();

    #pragma unroll
    for (int j = 0; j < 8; j++) {
        #pragma unroll
        for (int e = 0; e < 2; e++) {
            int col = 8 * j + 2 * tig + e;
            float v =    fmaxf(ac2[0][j][e]     + bz1[0], 0.f);
            v = fmaxf(v, fmaxf(ac2[0][j][e + 2] + bz1[1], 0.f));
            v = fmaxf(v, fmaxf(ac2[1][j][e]     + bz1[2], 0.f));
            v = fmaxf(v, fmaxf(ac2[1][j][e + 2] + bz1[3], 0.f));
            v = fmaxf(v, __shfl_xor_sync(0xffffffffu, v, 4));
            v = fmaxf(v, __shfl_xor_sync(0xffffffffu, v, 8));
            v = fmaxf(v, __shfl_xor_sync(0xffffffffu, v, 16));
            if (grp == 0) atomicMax(&sOutI[col], __float_as_int(v));
        }
    }
    __syncthreads();
    if (tid < TN) out[(size_t)b * N1 + n0 + tid] = __int_as_float(sOutI[tid]);
}

// ------------------- launch -------------------
extern "C" void kernel_launch(void* const* d_in, const int* in_sizes, int n_in,
                              void* d_out, int out_size) {
    const float* xyz1    = (const float*)d_in[0];
    const float* xyz2    = (const float*)d_in[1];
    const float* points2 = (const float*)d_in[2];
    const float* points1 = (const float*)d_in[3];
    const float* pb1     = (const float*)d_in[4];
    const float* w0  = (const float*)d_in[5];
    const float* b0  = (const float*)d_in[6];
    const float* g0  = (const float*)d_in[7];
    const float* be0 = (const float*)d_in[8];
    const float* m0  = (const float*)d_in[9];
    const float* v0  = (const float*)d_in[10];
    const float* w1  = (const float*)d_in[11];
    const float* b1  = (const float*)d_in[12];
    const float* g1  = (const float*)d_in[13];
    const float* be1 = (const float*)d_in[14];
    const float* m1  = (const float*)d_in[15];
    const float* v1  = (const float*)d_in[16];
    float* out = (float*)d_out;

    cudaFuncSetAttribute(mlp_kernel, cudaFuncAttributeMaxDynamicSharedMemorySize,
                         SMEM_MLP_BYTES);

    fold_kernel<<<(CH * CIN + 255) / 256, 256>>>(w0, b0, g0, be0, m0, v0,
                                                 w1, b1, g1, be1, m1, v1);
    pack_kernel<<<(BB * N2 + 255) / 256, 256>>>(xyz2);
    transpose_kernel<<<dim3(N2 / 32, CC / 32, BB), dim3(32, 8)>>>(points2);
    knn_part<<<dim3(N1 / 512, SEG, BB), 256>>>(xyz1);
    knn_merge<<<(BB * N1 + 255) / 256, 256>>>(xyz1);
    mlp_kernel<<<dim3(N1 / TN, BB), 256, SMEM_MLP_BYTES>>>(points1, pb1, out);
}

// round 10
// speedup vs baseline: 1.2701x; 1.0537x over previous
#include <cuda_runtime.h>
#include <cstdint>
#include <climits>

#define BB   4
#define N1   16384
#define N2   4096
#define CC   128
#define CIN  384
#define CH   256
#define TN   64
#define SEG  8
#define SEGN (N2 / SEG)          // 512 candidates, 128 quads per segment
#define QMASK 0xFFFFFF80u

#define SXS  72                  // X/Y row stride (floats): 72 % 32 == 8 -> conflict-free B frags
#define WT   1152                // per-warp per-buffer W tile: 32 oc x 36 floats (stride 36)
#define SX_FLOATS (CIN * SXS)    // 27648
#define SW_TOT    (8 * 3 * WT)   // 27648
#define SMEM_MLP_BYTES ((SX_FLOATS + SW_TOT + 64) * 4)   // 221440

// prep_kernel grid partition
#define PREP_T0   2048           // transpose blocks: 128 n-tiles x 4 c-tiles x 4 b
#define PREP_F0   (PREP_T0 + 384)  // fold blocks
#define PREP_END  (PREP_F0 + 64)   // pack blocks

// ------------------- scratch -------------------
__device__ float4 g_xyz2n[BB * N2];
__device__ uint4  g_pk[BB * SEG * N1];       // per-segment top-3 quad keys
__device__ float4 g_w4[BB * N1];
__device__ int4   g_i4[BB * N1];
__device__ float  g_p2t[BB * N2 * CC];
__device__ float  g_W0a[CH * CIN];           // folded W0 (oc, k) row-major, tf32
__device__ float  g_W1a[CH * CH];            // folded W1 (oc, k) row-major, tf32
__device__ float  g_b0f[CH];
__device__ float  g_b1f[CH];

// ------------------- helpers -------------------
__device__ __forceinline__ float cvt_tf32(float x) {
    unsigned u;
    asm("cvt.rna.tf32.f32 %0, %1;" : "=r"(u) : "f"(x));
    return __uint_as_float(u);
}

__device__ __forceinline__ void mma8(float* d, const unsigned* a, const unsigned* b) {
    asm("mma.sync.aligned.m16n8k8.row.col.f32.tf32.tf32.f32 "
        "{%0,%1,%2,%3}, {%4,%5,%6,%7}, {%8,%9}, {%0,%1,%2,%3};\n"
        : "+f"(d[0]), "+f"(d[1]), "+f"(d[2]), "+f"(d[3])
        : "r"(a[0]), "r"(a[1]), "r"(a[2]), "r"(a[3]), "r"(b[0]), "r"(b[1]));
}

__device__ __forceinline__ void cp16(float* s, const float* g) {
    unsigned sa = (unsigned)__cvta_generic_to_shared(s);
    asm volatile("cp.async.cg.shared.global [%0], [%1], 16;\n" :: "r"(sa), "l"(g));
}
#define CP_COMMIT() asm volatile("cp.async.commit_group;\n")
#define CPW1() asm volatile("cp.async.wait_group 1;\n")
#define CPW0() asm volatile("cp.async.wait_group 0;\n")

// sorted-3 insert over signed-int keys (5 min/max)
__device__ __forceinline__ void kins3(int k, int& K0, int& K1, int& K2) {
    int t0 = min(K0, k), u0 = max(K0, k);
    int t1 = min(K1, u0), u1 = max(K1, u0);
    K2 = min(K2, u1); K0 = t0; K1 = t1;
}
__device__ __forceinline__ void ins3(float s, int j,
                                     float& a0, float& a1, float& a2,
                                     int& i0, int& i1, int& i2) {
    if (s < a2) {
        if (s < a1) {
            a2 = a1; i2 = i1;
            if (s < a0) { a1 = a0; i1 = i0; a0 = s; i0 = j; }
            else        { a1 = s;  i1 = j; }
        } else { a2 = s; i2 = j; }
    }
}

// ------------------- K1: fused prep (transpose + fold + pack) -------------------
// blocks [0, 2048): transpose points2 (B,C,N2) -> (B,N2,C)
// blocks [2048, 2432): fold BN into W (oc,k) row-major tf32 + biases
// blocks [2432, 2496): pack xyz2 with norms
__global__ void __launch_bounds__(256) prep_kernel(
    const float* __restrict__ p2, const float* __restrict__ xyz2,
    const float* __restrict__ w0, const float* __restrict__ b0,
    const float* __restrict__ g0, const float* __restrict__ be0,
    const float* __restrict__ m0, const float* __restrict__ v0,
    const float* __restrict__ w1, const float* __restrict__ b1,
    const float* __restrict__ g1, const float* __restrict__ be1,
    const float* __restrict__ m1, const float* __restrict__ v1) {
    __shared__ float tile[32][33];
    int blk = blockIdx.x;
    int tid = threadIdx.x;

    if (blk < PREP_T0) {
        int b = blk >> 9;              // / 512
        int rem = blk & 511;
        int cb = (rem >> 7) * 32;      // 4 c-tiles
        int nb = (rem & 127) * 32;     // 128 n-tiles
        int tx = tid & 31, ty = tid >> 5;
        #pragma unroll
        for (int i = 0; i < 32; i += 8)
            tile[ty + i][tx] = p2[((size_t)b * CC + cb + ty + i) * N2 + nb + tx];
        __syncthreads();
        #pragma unroll
        for (int i = 0; i < 32; i += 8)
            g_p2t[((size_t)b * N2 + nb + ty + i) * CC + cb + tx] = tile[tx][ty + i];
    } else if (blk < PREP_F0) {
        int t = (blk - PREP_T0) * 256 + tid;
        if (t < CH * CIN) {
            int o = t / CIN;
            float s = g0[o] * rsqrtf(v0[o] + 1e-5f);
            g_W0a[t] = cvt_tf32(w0[t] * s);
        }
        if (t < CH * CH) {
            int o = t / CH;
            float s = g1[o] * rsqrtf(v1[o] + 1e-5f);
            g_W1a[t] = cvt_tf32(w1[t] * s);
        }
        if (t < CH) {
            float s0 = g0[t] * rsqrtf(v0[t] + 1e-5f);
            g_b0f[t] = (b0[t] - m0[t]) * s0 + be0[t];
            float s1 = g1[t] * rsqrtf(v1[t] + 1e-5f);
            g_b1f[t] = (b1[t] - m1[t]) * s1 + be1[t];
        }
    } else {
        int t = (blk - PREP_F0) * 256 + tid;
        if (t < BB * N2) {
            float x = xyz2[3 * t], y = xyz2[3 * t + 1], z = xyz2[3 * t + 2];
            g_xyz2n[t] = make_float4(x, y, z, x * x + y * y + z * z);
        }
    }
}

// ------------------- K2: quad-min 3-NN scan (SEG=8) -------------------
__global__ void __launch_bounds__(256) knn_part(const float* __restrict__ xyz1) {
    __shared__ float4 sP[SEGN];      // 8 KB
    int b = blockIdx.z, seg = blockIdx.y;
    int t = threadIdx.x;
    for (int i = t; i < SEGN; i += 256) sP[i] = g_xyz2n[b * N2 + seg * SEGN + i];
    __syncthreads();

    int q0 = blockIdx.x * 512 + t, q1 = q0 + 256;
    const float* p0 = xyz1 + ((size_t)b * N1 + q0) * 3;
    const float* p1 = xyz1 + ((size_t)b * N1 + q1) * 3;
    float x0 = p0[0], y0 = p0[1], z0 = p0[2];
    float x1 = p1[0], y1 = p1[1], z1 = p1[2];
    float ax0 = -2.f * x0, ay0 = -2.f * y0, az0 = -2.f * z0;
    float ax1 = -2.f * x1, ay1 = -2.f * y1, az1 = -2.f * z1;
    float nq0 = x0 * x0 + y0 * y0 + z0 * z0;
    float nq1 = x1 * x1 + y1 * y1 + z1 * z1;

    int A0 = INT_MAX, A1 = INT_MAX, A2 = INT_MAX;
    int B0 = INT_MAX, B1 = INT_MAX, B2 = INT_MAX;

    #pragma unroll 4
    for (int qd = 0; qd < SEGN / 4; qd++) {
        float4 pa = sP[4 * qd], pb = sP[4 * qd + 1];
        float4 pc = sP[4 * qd + 2], pe = sP[4 * qd + 3];
        float sa = fmaf(ax0, pa.x, fmaf(ay0, pa.y, fmaf(az0, pa.z, pa.w)));
        float sb = fmaf(ax0, pb.x, fmaf(ay0, pb.y, fmaf(az0, pb.z, pb.w)));
        float sc = fmaf(ax0, pc.x, fmaf(ay0, pc.y, fmaf(az0, pc.z, pc.w)));
        float se = fmaf(ax0, pe.x, fmaf(ay0, pe.y, fmaf(az0, pe.z, pe.w)));
        float m0 = fmaxf(fminf(fminf(sa, sb), fminf(sc, se)) + nq0, 0.f);
        kins3((int)((__float_as_uint(m0) & QMASK) | (unsigned)qd), A0, A1, A2);
        float ta = fmaf(ax1, pa.x, fmaf(ay1, pa.y, fmaf(az1, pa.z, pa.w)));
        float tb = fmaf(ax1, pb.x, fmaf(ay1, pb.y, fmaf(az1, pb.z, pb.w)));
        float tc = fmaf(ax1, pc.x, fmaf(ay1, pc.y, fmaf(az1, pc.z, pc.w)));
        float te = fmaf(ax1, pe.x, fmaf(ay1, pe.y, fmaf(az1, pe.z, pe.w)));
        float m1 = fmaxf(fminf(fminf(ta, tb), fminf(tc, te)) + nq1, 0.f);
        kins3((int)((__float_as_uint(m1) & QMASK) | (unsigned)qd), B0, B1, B2);
    }

    size_t o0 = (size_t)(b * SEG + seg) * N1 + q0;
    size_t o1 = (size_t)(b * SEG + seg) * N1 + q1;
    g_pk[o0] = make_uint4((unsigned)A0, (unsigned)A1, (unsigned)A2, 0u);
    g_pk[o1] = make_uint4((unsigned)B0, (unsigned)B1, (unsigned)B2, 0u);
}

// ------------------- K3: global top-3 quads + exact rescan -------------------
__global__ void knn_merge(const float* __restrict__ xyz1) {
    int t = blockIdx.x * blockDim.x + threadIdx.x;
    if (t >= BB * N1) return;
    int b = t / N1, q = t % N1;

    float D0 = 3.0e38f, D1 = 3.0e38f, D2 = 3.0e38f;
    int   G0 = 0, G1 = 0, G2 = 0;
    #pragma unroll
    for (int s = 0; s < SEG; s++) {
        uint4 k = g_pk[(size_t)(b * SEG + s) * N1 + q];
        unsigned kk[3] = {k.x, k.y, k.z};
        #pragma unroll
        for (int i = 0; i < 3; i++) {
            int gid = s * (SEGN / 4) + (int)(kk[i] & 127u);
            float d = __uint_as_float(kk[i] & QMASK);
            ins3(d, gid, D0, D1, D2, G0, G1, G2);
        }
    }

    float x = xyz1[3 * t], y = xyz1[3 * t + 1], z = xyz1[3 * t + 2];
    float nq = x * x + y * y + z * z;

    float A0 = 3.0e38f, A1 = 3.0e38f, A2 = 3.0e38f;
    int   I0 = 0, I1 = 0, I2 = 0;
    int gs[3] = {G0, G1, G2};
    #pragma unroll
    for (int i = 0; i < 3; i++) {
        int base = gs[i] * 4;
        #pragma unroll
        for (int c = 0; c < 4; c++) {
            float4 p = g_xyz2n[b * N2 + base + c];
            float d = nq + p.w - 2.f * (x * p.x + y * p.y + z * p.z);
            ins3(d, base + c, A0, A1, A2, I0, I1, I2);
        }
    }

    float w0 = 1.f / A0, w1 = 1.f / A1, w2 = 1.f / A2;
    float inv = 1.f / (w0 + w1 + w2);
    g_w4[t] = make_float4(w0 * inv, w1 * inv, w2 * inv, 0.f);
    g_i4[t] = make_int4(I0, I1, I2, 0);
}

// ------------------- MLP building blocks -------------------
// Per-warp W chunk stream: warp's own 32 oc rows x 32 k, dest tile [oc][k] stride 36.
__device__ __forceinline__ void issue_w(int c, int warp, int lane, float* sW) {
    const float* src; int Ksrc, kc;
    if (c < 12) { src = g_W0a; Ksrc = CIN; kc = c * 32; }
    else        { src = g_W1a; Ksrc = CH;  kc = (c - 12) * 32; }
    float* dst = sW + warp * (3 * WT) + (c % 3) * WT;
    int Rw = warp * 32;
    #pragma unroll
    for (int i = 0; i < 8; i++) {
        int idx = lane + 32 * i;            // 0..255 = 32 oc x 8 k-quads
        int ocl = idx >> 3, kq = idx & 7;
        cp16(dst + ocl * 36 + kq * 4, src + (size_t)(Rw + ocl) * Ksrc + kc + kq * 4);
    }
    CP_COMMIT();
}

// A frags from per-warp [oc][k] stride-36 tile ((4*oc+k) % 32 distinct -> conflict-free)
__device__ __forceinline__ void gemm_chunk(const float* wt, const float* sB,
                                           int lane, float acc[2][8][4]) {
    int grp = lane >> 2, tig = lane & 3;
    #pragma unroll
    for (int ks = 0; ks < 4; ks++) {
        int k8 = ks * 8;
        unsigned a[2][4], bf[8][2];
        #pragma unroll
        for (int m = 0; m < 2; m++) {
            const float* r0 = wt + (m * 16 + grp) * 36;
            const float* r8 = wt + (m * 16 + grp + 8) * 36;
            a[m][0] = __float_as_uint(r0[k8 + tig]);
            a[m][1] = __float_as_uint(r8[k8 + tig]);
            a[m][2] = __float_as_uint(r0[k8 + tig + 4]);
            a[m][3] = __float_as_uint(r8[k8 + tig + 4]);
        }
        const float* x0r = sB + (k8 + tig) * SXS;
        const float* x4r = sB + (k8 + tig + 4) * SXS;
        #pragma unroll
        for (int j = 0; j < 8; j++) {
            int cb = j * 8 + grp;
            bf[j][0] = __float_as_uint(x0r[cb]);
            bf[j][1] = __float_as_uint(x4r[cb]);
        }
        #pragma unroll
        for (int m = 0; m < 2; m++)
            #pragma unroll
            for (int j = 0; j < 8; j++)
                mma8(acc[m][j], a[m], bf[j]);
    }
}

// ------------------- K4: fused MLP + channel max (warp-private W pipeline) -------------------
__global__ void __launch_bounds__(256, 1)
mlp_kernel(const float* __restrict__ points1, const float* __restrict__ pb1,
           float* __restrict__ out) {
    extern __shared__ float sm[];
    float* sX   = sm;                         // [384][SXS]; rows 0..255 reused as Y
    float* sW   = sm + SX_FLOATS;             // 8 warps x 3 bufs x WT
    int*   sOutI = (int*)(sm + SX_FLOATS + SW_TOT);

    int b  = blockIdx.y;
    int n0 = blockIdx.x * TN;
    int tid = threadIdx.x;
    int warp = tid >> 5, lane = tid & 31;
    int grp = lane >> 2, tig = lane & 3;
    int Rw = warp * 32;

    // per-warp prefetch of first two W chunks
    issue_w(0, warp, lane, sW);
    issue_w(1, warp, lane, sW);

    // ---- Phase A: build X (384 x 64) ----
    for (int idx = tid; idx < CC * TN; idx += 256) {
        int c = idx >> 6, n = idx & 63;
        sX[c * SXS + n]         = cvt_tf32(points1[((size_t)b * CC + c) * N1 + n0 + n]);
        sX[(c + 256) * SXS + n] = cvt_tf32(pb1[((size_t)b * CC + c) * N1 + n0 + n]);
    }
    for (int qq = 0; qq < 8; qq++) {
        int q = warp * 8 + qq;
        int n = n0 + q;
        float4 wv = g_w4[b * N1 + n];
        int4   iv = g_i4[b * N1 + n];
        const float* r0 = &g_p2t[((size_t)b * N2 + iv.x) * CC];
        const float* r1 = &g_p2t[((size_t)b * N2 + iv.y) * CC];
        const float* r2 = &g_p2t[((size_t)b * N2 + iv.z) * CC];
        #pragma unroll
        for (int i = 0; i < 4; i++) {
            int c = lane + 32 * i;
            float v = wv.x * r0[c] + wv.y * r1[c] + wv.z * r2[c];
            sX[(128 + c) * SXS + q] = cvt_tf32(v);
        }
    }
    __syncthreads();

    // ---- GEMM1: barrier-free, per-warp W pipeline over 12 chunks ----
    float acc[2][8][4];
    #pragma unroll
    for (int m = 0; m < 2; m++)
        #pragma unroll
        for (int j = 0; j < 8; j++)
            #pragma unroll
            for (int e = 0; e < 4; e++) acc[m][j][e] = 0.f;

    for (int c = 0; c < 12; c++) {
        CPW1();
        issue_w(c + 2, warp, lane, sW);    // prefetch before compute: longer overlap
        gemm_chunk(sW + warp * (3 * WT) + (c % 3) * WT, sX + c * 32 * SXS, lane, acc);
    }
    __syncthreads();   // all warps done reading X rows 0..255 before Y overwrites them

    // ---- epilogue 1: bias + ReLU -> Y (rows 0..255 of sX region, warp's own rows) ----
    {
        float bz[4];
        #pragma unroll
        for (int i = 0; i < 4; i++) bz[i] = g_b0f[Rw + grp + 8 * i];
        float* sY = sm;
        #pragma unroll
        for (int m = 0; m < 2; m++)
            #pragma unroll
            for (int j = 0; j < 8; j++) {
                int r0 = Rw + 16 * m + grp;
                int col = 8 * j + 2 * tig;
                sY[r0 * SXS + col]           = cvt_tf32(fmaxf(acc[m][j][0] + bz[2 * m], 0.f));
                sY[r0 * SXS + col + 1]       = cvt_tf32(fmaxf(acc[m][j][1] + bz[2 * m], 0.f));
                sY[(r0 + 8) * SXS + col]     = cvt_tf32(fmaxf(acc[m][j][2] + bz[2 * m + 1], 0.f));
                sY[(r0 + 8) * SXS + col + 1] = cvt_tf32(fmaxf(acc[m][j][3] + bz[2 * m + 1], 0.f));
            }
    }
    __syncthreads();   // Y visible to all before GEMM2 reads

    // ---- GEMM2: barrier-free, chunks 12..19 ----
    float ac2[2][8][4];
    #pragma unroll
    for (int m = 0; m < 2; m++)
        #pragma unroll
        for (int j = 0; j < 8; j++)
            #pragma unroll
            for (int e = 0; e < 4; e++) ac2[m][j][e] = 0.f;

    for (int c = 12; c < 20; c++) {
        if (c == 19) { CPW0(); } else { CPW1(); }
        if (c + 2 < 20) issue_w(c + 2, warp, lane, sW);
        gemm_chunk(sW + warp * (3 * WT) + (c % 3) * WT, sm + (c - 12) * 32 * SXS, lane, ac2);
    }

    // ---- epilogue 2: bias + ReLU + channel max ----
    float bz1[4];
    #pragma unroll
    for (int i = 0; i < 4; i++) bz1[i] = g_b1f[Rw + grp + 8 * i];

    if (tid < TN) sOutI[tid] = 0;   // ReLU output >= 0 -> int 0 valid identity
    __syncthreads();

    #pragma unroll
    for (int j = 0; j < 8; j++) {
        #pragma unroll
        for (int e = 0; e < 2; e++) {
            int col = 8 * j + 2 * tig + e;
            float v =    fmaxf(ac2[0][j][e]     + bz1[0], 0.f);
            v = fmaxf(v, fmaxf(ac2[0][j][e + 2] + bz1[1], 0.f));
            v = fmaxf(v, fmaxf(ac2[1][j][e]     + bz1[2], 0.f));
            v = fmaxf(v, fmaxf(ac2[1][j][e + 2] + bz1[3], 0.f));
            v = fmaxf(v, __shfl_xor_sync(0xffffffffu, v, 4));
            v = fmaxf(v, __shfl_xor_sync(0xffffffffu, v, 8));
            v = fmaxf(v, __shfl_xor_sync(0xffffffffu, v, 16));
            if (grp == 0) atomicMax(&sOutI[col], __float_as_int(v));
        }
    }
    __syncthreads();
    if (tid < TN) out[(size_t)b * N1 + n0 + tid] = __int_as_float(sOutI[tid]);
}

// ------------------- launch -------------------
extern "C" void kernel_launch(void* const* d_in, const int* in_sizes, int n_in,
                              void* d_out, int out_size) {
    const float* xyz1    = (const float*)d_in[0];
    const float* xyz2    = (const float*)d_in[1];
    const float* points2 = (const float*)d_in[2];
    const float* points1 = (const float*)d_in[3];
    const float* pb1     = (const float*)d_in[4];
    const float* w0  = (const float*)d_in[5];
    const float* b0  = (const float*)d_in[6];
    const float* g0  = (const float*)d_in[7];
    const float* be0 = (const float*)d_in[8];
    const float* m0  = (const float*)d_in[9];
    const float* v0  = (const float*)d_in[10];
    const float* w1  = (const float*)d_in[11];
    const float* b1  = (const float*)d_in[12];
    const float* g1  = (const float*)d_in[13];
    const float* be1 = (const float*)d_in[14];
    const float* m1  = (const float*)d_in[15];
    const float* v1  = (const float*)d_in[16];
    float* out = (float*)d_out;

    cudaFuncSetAttribute(mlp_kernel, cudaFuncAttributeMaxDynamicSharedMemorySize,
                         SMEM_MLP_BYTES);

    prep_kernel<<<PREP_END, 256>>>(points2, xyz2,
                                   w0, b0, g0, be0, m0, v0,
                                   w1, b1, g1, be1, m1, v1);
    knn_part<<<dim3(N1 / 512, SEG, BB), 256>>>(xyz1);
    knn_merge<<<(BB * N1 + 255) / 256, 256>>>(xyz1);
    mlp_kernel<<<dim3(N1 / TN, BB), 256, SMEM_MLP_BYTES>>>(points1, pb1, out);
}